// round 15
// baseline (speedup 1.0000x reference)
#include <cuda_runtime.h>
#include <math.h>

#define BATCH 16
#define NA 21824            // total anchors per image: 16384+4096+1024+256+64
#define NV4 5456            // NA/4
#define NCAP 1024           // collected candidate capacity (top-256 exact + 768 tie bucket)
#define NSORTED 512         // candidates pre-gathered + fed to NMS
#define FULLMASK 0xffffffffu
#define PADKEY 0x7FFFFFFFULL   // score bits 0, anchor field 0x7FFFFFFF -> anchor 0

// ---------------- scratch (device globals; zero-initialized at load) -------
// Every launch leaves these zeroed again (final phase self-cleans), so the
// pipeline is deterministic across harness replays.
__device__ float  g_scores[BATCH * NA];
__device__ int    g_classes[BATCH * NA];
__device__ float4 g_boxes[BATCH * NA];
__device__ unsigned g_histA[BATCH][2048];     // top 11 bits of score pattern
__device__ unsigned g_histB[BATCH][65536];    // top 16 bits of score pattern
__device__ unsigned long long g_keys[BATCH][NCAP];
__device__ unsigned g_cnt[BATCH][2];          // [0]=count(>B), [1]=count(==B bucket)
__device__ unsigned g_bar[BATCH];             // collect-done arrivals (last-arrival barrier)

struct DecodeParams {
    const float* cls[5];
    const float* reg[5];
    const float* ctr[5];
    const float* pos[5];
};

// warp-aggregated histogram add (all 32 lanes active)
__device__ __forceinline__ void hadd(unsigned* hist, unsigned bin) {
    unsigned m = __match_any_sync(FULLMASK, bin);
    int lane = threadIdx.x & 31;
    if (lane == __ffs(m) - 1) atomicAdd(&hist[bin], (unsigned)__popc(m));
}

// ---------------- K1: decode (64 anchors per 256-thread block) -------------
#define DEC_ANCHORS 64
#define DEC_T 256
#define SM_STRIDE 88        // floats per anchor row in smem (16B aligned, low conflicts)

__global__ void __launch_bounds__(DEC_T) decode_kernel(DecodeParams P) {
    __shared__ float sd[DEC_ANCHORS * SM_STRIDE];
    __shared__ float svmax[DEC_ANCHORS];
    __shared__ int   scls[DEC_ANCHORS];

    int img = blockIdx.y;
    int A0  = blockIdx.x * DEC_ANCHORS;
    int tid = threadIdx.x;

    int lev, off, HW;
    if      (A0 < 16384) { lev = 0; off = 0;     HW = 16384; }
    else if (A0 < 20480) { lev = 1; off = 16384; HW = 4096; }
    else if (A0 < 21504) { lev = 2; off = 20480; HW = 1024; }
    else if (A0 < 21760) { lev = 3; off = 21504; HW = 256; }
    else                 { lev = 4; off = 21760; HW = 64; }

    long base = (long)img * HW + (A0 - off);

    // stage 64 anchors x 80 floats = 1280 float4s, coalesced
    const float4* cf4 = reinterpret_cast<const float4*>(P.cls[lev]) + base * 20;
    #pragma unroll
    for (int r = 0; r < 5; r++) {
        int g = tid + r * DEC_T;          // 0..1279
        float4 q = cf4[g];
        int a = g / 20;
        int m = g - a * 20;
        *reinterpret_cast<float4*>(&sd[a * SM_STRIDE + m * 4]) = q;
    }
    __syncthreads();

    // scan: 4 threads per anchor, 20 logits each
    {
        int a = tid >> 2, p = tid & 3;
        const float4* row = reinterpret_cast<const float4*>(&sd[a * SM_STRIDE + p * 20]);
        float v = -INFINITY; int ci = 0x7fffffff;
        #pragma unroll
        for (int u = 0; u < 5; u++) {
            float4 q = row[u];
            int c = p * 20 + u * 4;
            if (q.x > v) { v = q.x; ci = c; }
            if (q.y > v) { v = q.y; ci = c + 1; }
            if (q.z > v) { v = q.z; ci = c + 2; }
            if (q.w > v) { v = q.w; ci = c + 3; }
        }
        #pragma unroll
        for (int o = 1; o < 4; o <<= 1) {
            float ov = __shfl_xor_sync(FULLMASK, v, o);
            int   oi = __shfl_xor_sync(FULLMASK, ci, o);
            if (ov > v || (ov == v && oi < ci)) { v = ov; ci = oi; }
        }
        if (p == 0) { svmax[a] = v; scls[a] = ci; }
    }
    __syncthreads();

    // epilogue: one anchor per thread (threads 0..63, two full warps)
    if (tid < DEC_ANCHORS) {
        long bi = base + tid;
        float ct = P.ctr[lev][bi];
        float v  = svmax[tid];
        float sm  = 1.f / (1.f + expf(-v));
        float sct = 1.f / (1.f + expf(-ct));
        float s   = sqrtf(sm * sct);

        float4 rg = reinterpret_cast<const float4*>(P.reg[lev])[bi];
        float2 pp = reinterpret_cast<const float2*>(P.pos[lev])[bi];
        float e0 = expf(rg.x), e1 = expf(rg.y), e2 = expf(rg.z), e3 = expf(rg.w);
        int x1 = max((int)(pp.x - e0), 0);
        int y1 = max((int)(pp.y - e1), 0);
        int x2 = min((int)(pp.x + e2), 1023);
        int y2 = min((int)(pp.y + e3), 1023);

        int gi = img * NA + A0 + tid;
        g_scores[gi]  = s;
        g_classes[gi] = scls[tid];
        g_boxes[gi]   = make_float4((float)x1, (float)y1, (float)x2, (float)y2);

        // inline histograms: coarse (11-bit) + fine (16-bit), warp-aggregated
        unsigned u = __float_as_uint(s);
        hadd(&g_histA[img][0], u >> 21);
        hadd(&g_histB[img][0], u >> 16);
    }
}

// find highest bin where suffix count crosses `need` (hist in SHARED memory)
__device__ __forceinline__ void find_bin_sh(const unsigned* hist, unsigned need,
                                            unsigned* chunkSum, unsigned* outB,
                                            unsigned* outAbove, int tid) {
    if (tid < 64) {
        unsigned s = 0;
        #pragma unroll
        for (int b = 0; b < 32; b++) s += hist[tid * 32 + b];
        chunkSum[tid] = s;
    }
    __syncthreads();
    if (tid == 0) {
        unsigned run = 0;
        for (int c = 63; c >= 0; c--) { unsigned t = chunkSum[c]; chunkSum[c] = run; run += t; }
    }
    __syncthreads();
    if (tid < 64) {
        unsigned above = chunkSum[tid];
        #pragma unroll
        for (int b = 31; b >= 0; b--) {
            unsigned h = hist[tid * 32 + b];
            if (above < need && above + h >= need) { *outB = (unsigned)(tid * 32 + b); *outAbove = above; }
            above += h;
        }
    }
    __syncthreads();
}

__device__ __forceinline__ bool iou_gt(float kx1, float ky1, float kx2, float ky2, float ka,
                                       float x1, float y1, float x2, float y2, float ca) {
    float xx1 = fmaxf(kx1, x1), yy1 = fmaxf(ky1, y1);
    float xx2 = fminf(kx2, x2), yy2 = fminf(ky2, y2);
    float inter = fmaxf(xx2 - xx1, 0.f) * fmaxf(yy2 - yy1, 0.f);
    float iou = inter / (ka + ca - inter);          // 0/0 -> NaN -> not suppressed (matches JAX)
    return iou > 0.6f;
}

// ---------------- K2 (fused): threshold + collect + rank sort + NMS --------
#define FUSE_T 512
#define FUSE_SLICES 4
#define FUSE_ROUNDS 3      // ceil(NV4 / (FUSE_T*FUSE_SLICES))
#define CHUNK 64

__global__ void __launch_bounds__(FUSE_T) fused_kernel(float* __restrict__ out) {
    __shared__ unsigned h[2048];
    __shared__ unsigned chunkSum[64];
    __shared__ unsigned shb[32];
    __shared__ unsigned sB1, sAb1, sB16;
    __shared__ int sLast;
    __shared__ unsigned long long keys[NCAP];
    __shared__ unsigned long long sorted[NCAP];
    // preloaded candidate state (final phase, top NSORTED)
    __shared__ float Bx1[NSORTED], By1[NSORTED], Bx2[NSORTED], By2[NSORTED];
    __shared__ float Sar[NSORTED], Ssc[NSORTED];
    __shared__ int   Scl[NSORTED];
    // NMS shared state
    __shared__ float kx1[100], ky1[100], kx2[100], ky2[100], ka[100];
    __shared__ int   supk[CHUNK];
    __shared__ unsigned long long mask[CHUNK];
    __shared__ int   kl[CHUNK];
    __shared__ unsigned sFlag[2];
    __shared__ int   sNew, sNK, sDone, sFast;

    int img = blockIdx.y;
    int tid = threadIdx.x;

    // slice-0 block prefills the output rows (off the final critical path;
    // ordered before final writes by the last-arrival barrier + fences)
    if (blockIdx.x == 0) {
        if (tid < 100) {
            out[img * 100 + tid]        = -1.f;
            out[1600 + img * 100 + tid] = -1.f;
        }
        for (int q = tid; q < 400; q += FUSE_T)
            out[3200 + img * 400 + q] = -1.f;
    }

    // ---- threshold: coarse bin from histA, refine with 32 histB sub-bins --
    for (int i = tid; i < 2048; i += FUSE_T) h[i] = g_histA[img][i];
    __syncthreads();
    find_bin_sh(h, 256u, chunkSum, &sB1, &sAb1, tid);
    if (tid < 32) shb[tid] = g_histB[img][sB1 * 32 + tid];
    __syncthreads();
    if (tid == 0) {
        unsigned above = sAb1;
        unsigned bsel = sB1 * 32;
        for (int sb = 31; sb >= 0; sb--) {
            unsigned hh = shb[sb];
            if (above < 256u && above + hh >= 256u) bsel = sB1 * 32 + (unsigned)sb;
            above += hh;
        }
        sB16 = bsel;
    }
    __syncthreads();
    unsigned B = sB16;                 // 16-bit threshold key

    // ---- collect: one pass over this block's slice of the scores ----------
    const float4* sc4 = reinterpret_cast<const float4*>(g_scores + img * NA);
    #pragma unroll
    for (int it = 0; it < FUSE_ROUNDS; it++) {
        int j = blockIdx.x * FUSE_T + tid + it * (FUSE_T * FUSE_SLICES);
        bool valid = j < NV4;
        float4 q = valid ? sc4[j] : make_float4(0.f, 0.f, 0.f, 0.f);
        float v[4] = {q.x, q.y, q.z, q.w};
        #pragma unroll
        for (int c = 0; c < 4; c++) {
            unsigned u = __float_as_uint(v[c]);
            unsigned k16 = u >> 16;
            if (valid && k16 >= B) {
                // key = (score_bits << 32) | (0x7FFFFFFF - anchor): ties ->
                // ascending anchor, matching the reference's stable order.
                unsigned long long key = ((unsigned long long)u << 32) |
                                         (unsigned)(0x7FFFFFFF - (4 * j + c));
                if (k16 > B) {
                    unsigned s = atomicAdd(&g_cnt[img][0], 1u);   // global >B count < 256
                    g_keys[img][s] = key;
                } else {
                    unsigned s = atomicAdd(&g_cnt[img][1], 1u);   // tie bucket
                    if (256u + s < NCAP) g_keys[img][256u + s] = key;
                }
            }
        }
    }

    // ---- last-arrival barrier: final phase runs in the last block ----------
    __threadfence();
    __syncthreads();
    if (tid == 0) {
        unsigned old = atomicAdd(&g_bar[img], 1u);
        sLast = (old == (unsigned)(FUSE_SLICES - 1));
    }
    __syncthreads();
    if (!sLast) return;
    __threadfence();

    // =================== FINAL PHASE (one block per image) ===================

    // load keys (count-masked; stale/unwritten slots -> PADKEY)
    unsigned gt = g_cnt[img][0];
    unsigned eq = g_cnt[img][1];
    {
        bool r0 = (unsigned)tid < gt;
        bool r1 = (unsigned)tid < ((eq < 768u) ? eq : 768u);
        keys[tid]         = r0 ? g_keys[img][tid] : PADKEY;
        keys[tid + 512]   = r1 ? g_keys[img][tid + 512] : PADKEY;   // wait: tie bucket starts at 256
        sorted[tid]       = PADKEY;
        sorted[tid + 512] = PADKEY;
    }
    // fix tie-bucket mapping: slots 256..1023 hold tie keys 0..767
    {
        // re-load slots 256..511 region correctly (overwrites the r1 approximation above)
        int t2 = tid + 256;                       // shared slots 256..767
        bool real = (unsigned)tid < ((eq < 768u) ? eq : 768u);
        keys[t2 < NCAP ? t2 : NCAP - 1] = real && (t2 < NCAP) ? g_keys[img][t2] : keys[t2 < NCAP ? t2 : NCAP - 1];
        if (!real && t2 < NCAP) keys[t2] = PADKEY;
        // slots 768..1023: tie keys 512..767
        int t3 = tid + 768;
        if (tid < 256) {
            bool real3 = (unsigned)(tid + 512) < ((eq < 768u) ? eq : 768u);
            keys[t3] = real3 ? g_keys[img][t3] : PADKEY;
        }
    }

    // self-clean scratch for the next launch (fire-and-forget stores)
    for (int i = tid; i < 2048; i += FUSE_T) g_histA[img][i] = 0;
    {
        uint4 z = make_uint4(0, 0, 0, 0);
        uint4* hb4 = reinterpret_cast<uint4*>(&g_histB[img][0]);
        #pragma unroll
        for (int r = 0; r < 65536 / 4 / FUSE_T; r++)
            hb4[tid + r * FUSE_T] = z;
    }
    if (tid < 2) g_cnt[img][tid] = 0;
    if (tid == 2) g_bar[img] = 0;
    __syncthreads();

    // rank sort: 2 keys per thread over NCAP=1024; rank = #(strictly greater)
    {
        unsigned long long my0 = keys[tid];
        unsigned long long my1 = keys[tid + 512];
        const ulonglong2* K2 = reinterpret_cast<const ulonglong2*>(keys);
        int r0 = 0, r1 = 0;
        #pragma unroll 8
        for (int j2 = 0; j2 < NCAP / 2; j2++) {
            ulonglong2 p = K2[j2];
            r0 += (p.x > my0) + (p.y > my0);
            r1 += (p.x > my1) + (p.y > my1);
        }
        sorted[r0] = my0;   // unique real keys -> dense exact ranks; pads collide benignly
        sorted[r1] = my1;
    }
    __syncthreads();

    // pre-gather top NSORTED candidate boxes/classes in one full-MLP pass
    if (tid < NSORTED) {
        unsigned long long it = sorted[tid];
        float s = __uint_as_float((unsigned)(it >> 32));
        int anc = 0x7FFFFFFF - (int)(unsigned)(it & 0xffffffffULL);
        float4 bx = g_boxes[img * NA + anc];
        Bx1[tid] = bx.x; By1[tid] = bx.y; Bx2[tid] = bx.z; By2[tid] = bx.w;
        Sar[tid] = (bx.z - bx.x) * (bx.w - bx.y);
        Scl[tid] = g_classes[img * NA + anc];
        Ssc[tid] = s;
    }
    __syncthreads();

    // NMS over sorted candidates (all state in shared)
    if (tid == 0) { sNK = 0; sDone = 0; }
    __syncthreads();

    for (int base = 0; base < NSORTED; base += CHUNK) {
        if (sDone) break;

        if (tid < CHUNK) { supk[tid] = 0; mask[tid] = 0ULL; }
        __syncthreads();

        int nk = sNK;
        {
            int c = tid & (CHUNK - 1);
            int part = tid >> 6;            // 0..7
            float x1 = Bx1[base + c], y1 = By1[base + c];
            float x2 = Bx2[base + c], y2 = By2[base + c], ar = Sar[base + c];
            bool any = false;
            for (int j = part; j < nk; j += 8)
                any |= iou_gt(kx1[j], ky1[j], kx2[j], ky2[j], ka[j], x1, y1, x2, y2, ar);
            if (any) supk[c] = 1;           // benign race: all writers store 1
        }

        for (int p = tid; p < CHUNK * CHUNK; p += FUSE_T) {
            int c = p >> 6, j = p & (CHUNK - 1);
            if (c < j) {
                if (iou_gt(Bx1[base + c], By1[base + c], Bx2[base + c], By2[base + c], Sar[base + c],
                           Bx1[base + j], By1[base + j], Bx2[base + j], By2[base + j], Sar[base + j]))
                    atomicOr(&mask[c], 1ULL << j);
            }
        }
        __syncthreads();

        // fast path: no suppression anywhere in chunk and all scores valid
        if (tid < CHUNK) {
            bool bad = supk[tid] || (mask[tid] != 0ULL) || (Ssc[base + tid] <= 0.01f);
            unsigned bb = __ballot_sync(FULLMASK, bad);
            if ((tid & 31) == 0) sFlag[tid >> 5] = bb;
        }
        __syncthreads();

        if (tid == 0) {
            if ((sFlag[0] | sFlag[1]) == 0u) {
                int nnew = min(CHUNK, 100 - sNK);
                sNew = nnew; sFast = 1;
                if (sNK + nnew >= 100) sDone = 1;
            } else {
                sFast = 0;
                unsigned long long sup = 0;
                int nnew = 0;
                int done = 0;
                for (int c = 0; c < CHUNK; c++) {
                    if (Ssc[base + c] <= 0.01f) { done = 1; break; }  // sorted -> rest invalid
                    if (supk[c] || ((sup >> c) & 1ULL)) continue;
                    kl[nnew++] = c;
                    sup |= mask[c];
                    if (sNK + nnew == 100) { done = 1; break; }
                }
                sNew = nnew;
                if (done) sDone = 1;
            }
        }
        __syncthreads();

        if (tid < sNew) {
            int c = base + (sFast ? tid : kl[tid]);
            int pos = sNK + tid;
            kx1[pos] = Bx1[c]; ky1[pos] = By1[c];
            kx2[pos] = Bx2[c]; ky2[pos] = By2[c];
            ka[pos]  = Sar[c];
            out[img * 100 + pos]        = Ssc[c];
            out[1600 + img * 100 + pos] = (float)Scl[c];
            int ob = 3200 + img * 400 + pos * 4;
            out[ob]     = Bx1[c];
            out[ob + 1] = By1[c];
            out[ob + 2] = Bx2[c];
            out[ob + 3] = By2[c];
        }
        __syncthreads();
        if (tid == 0) sNK += sNew;
        __syncthreads();
    }
}

// ---------------- launch ---------------------------------------------------
extern "C" void kernel_launch(void* const* d_in, const int* in_sizes, int n_in,
                              void* d_out, int out_size) {
    DecodeParams P;
    for (int l = 0; l < 5; l++) {
        P.cls[l] = (const float*)d_in[4 * l + 0];
        P.reg[l] = (const float*)d_in[4 * l + 1];
        P.ctr[l] = (const float*)d_in[4 * l + 2];
        P.pos[l] = (const float*)d_in[4 * l + 3];
    }
    dim3 dgrid(341, BATCH);
    decode_kernel<<<dgrid, DEC_T>>>(P);
    dim3 fgrid(FUSE_SLICES, BATCH);
    fused_kernel<<<fgrid, FUSE_T>>>((float*)d_out);
}

// round 16
// speedup vs baseline: 1.2350x; 1.2350x over previous
#include <cuda_runtime.h>
#include <math.h>

#define BATCH 16
#define NA 21824            // total anchors per image: 16384+4096+1024+256+64
#define NV4 5456            // NA/4
#define NCAP 512            // collected candidate capacity (top-256 + tie bucket)
#define FULLMASK 0xffffffffu
#define PADKEY 0x7FFFFFFFULL   // score bits 0, anchor field 0x7FFFFFFF -> anchor 0

// ---------------- scratch (device globals; zero-initialized at load) -------
// Every launch leaves these zeroed again (final phase self-cleans), so the
// pipeline is deterministic across harness replays.
__device__ float  g_scores[BATCH * NA];
__device__ int    g_classes[BATCH * NA];
__device__ float4 g_boxes[BATCH * NA];
__device__ unsigned g_histA[BATCH][2048];     // top 11 bits of score pattern
__device__ unsigned long long g_keys[BATCH][NCAP];
__device__ unsigned g_cnt[BATCH][2];          // [0]=count(>B), [1]=count(==B bucket)
__device__ unsigned g_bar[BATCH];             // collect-done arrivals (last-arrival barrier)

struct DecodeParams {
    const float* cls[5];
    const float* reg[5];
    const float* ctr[5];
    const float* pos[5];
};

// warp-aggregated histogram add (all 32 lanes active)
__device__ __forceinline__ void hadd(unsigned* hist, unsigned bin) {
    unsigned m = __match_any_sync(FULLMASK, bin);
    int lane = threadIdx.x & 31;
    if (lane == __ffs(m) - 1) atomicAdd(&hist[bin], (unsigned)__popc(m));
}

// ---------------- K1: decode (64 anchors per 256-thread block) -------------
#define DEC_ANCHORS 64
#define DEC_T 256
#define SM_STRIDE 88        // floats per anchor row in smem (16B aligned, low conflicts)

__global__ void __launch_bounds__(DEC_T) decode_kernel(DecodeParams P) {
    __shared__ float sd[DEC_ANCHORS * SM_STRIDE];
    __shared__ float svmax[DEC_ANCHORS];
    __shared__ int   scls[DEC_ANCHORS];

    int img = blockIdx.y;
    int A0  = blockIdx.x * DEC_ANCHORS;
    int tid = threadIdx.x;

    int lev, off, HW;
    if      (A0 < 16384) { lev = 0; off = 0;     HW = 16384; }
    else if (A0 < 20480) { lev = 1; off = 16384; HW = 4096; }
    else if (A0 < 21504) { lev = 2; off = 20480; HW = 1024; }
    else if (A0 < 21760) { lev = 3; off = 21504; HW = 256; }
    else                 { lev = 4; off = 21760; HW = 64; }

    long base = (long)img * HW + (A0 - off);

    // stage 64 anchors x 80 floats = 1280 float4s, coalesced
    const float4* cf4 = reinterpret_cast<const float4*>(P.cls[lev]) + base * 20;
    #pragma unroll
    for (int r = 0; r < 5; r++) {
        int g = tid + r * DEC_T;          // 0..1279
        float4 q = cf4[g];
        int a = g / 20;
        int m = g - a * 20;
        *reinterpret_cast<float4*>(&sd[a * SM_STRIDE + m * 4]) = q;
    }
    __syncthreads();

    // scan: 4 threads per anchor, 20 logits each
    {
        int a = tid >> 2, p = tid & 3;
        const float4* row = reinterpret_cast<const float4*>(&sd[a * SM_STRIDE + p * 20]);
        float v = -INFINITY; int ci = 0x7fffffff;
        #pragma unroll
        for (int u = 0; u < 5; u++) {
            float4 q = row[u];
            int c = p * 20 + u * 4;
            if (q.x > v) { v = q.x; ci = c; }
            if (q.y > v) { v = q.y; ci = c + 1; }
            if (q.z > v) { v = q.z; ci = c + 2; }
            if (q.w > v) { v = q.w; ci = c + 3; }
        }
        #pragma unroll
        for (int o = 1; o < 4; o <<= 1) {
            float ov = __shfl_xor_sync(FULLMASK, v, o);
            int   oi = __shfl_xor_sync(FULLMASK, ci, o);
            if (ov > v || (ov == v && oi < ci)) { v = ov; ci = oi; }
        }
        if (p == 0) { svmax[a] = v; scls[a] = ci; }
    }
    __syncthreads();

    // epilogue: one anchor per thread (threads 0..63, two full warps)
    if (tid < DEC_ANCHORS) {
        long bi = base + tid;
        float ct = P.ctr[lev][bi];
        float v  = svmax[tid];
        float sm  = 1.f / (1.f + expf(-v));
        float sct = 1.f / (1.f + expf(-ct));
        float s   = sqrtf(sm * sct);

        float4 rg = reinterpret_cast<const float4*>(P.reg[lev])[bi];
        float2 pp = reinterpret_cast<const float2*>(P.pos[lev])[bi];
        float e0 = expf(rg.x), e1 = expf(rg.y), e2 = expf(rg.z), e3 = expf(rg.w);
        int x1 = max((int)(pp.x - e0), 0);
        int y1 = max((int)(pp.y - e1), 0);
        int x2 = min((int)(pp.x + e2), 1023);
        int y2 = min((int)(pp.y + e3), 1023);

        int gi = img * NA + A0 + tid;
        g_scores[gi]  = s;
        g_classes[gi] = scls[tid];
        g_boxes[gi]   = make_float4((float)x1, (float)y1, (float)x2, (float)y2);

        // inline pass-1 histogram (top 11 bits of score pattern), warp-aggregated
        hadd(&g_histA[img][0], __float_as_uint(s) >> 21);
    }
}

// find highest bin where suffix count crosses `need` (hist in SHARED memory)
__device__ __forceinline__ void find_bin_sh(const unsigned* hist, unsigned need,
                                            unsigned* chunkSum, unsigned* outB,
                                            unsigned* outAbove, int tid) {
    if (tid < 64) {
        unsigned s = 0;
        #pragma unroll
        for (int b = 0; b < 32; b++) s += hist[tid * 32 + b];
        chunkSum[tid] = s;
    }
    __syncthreads();
    if (tid == 0) {
        unsigned run = 0;
        for (int c = 63; c >= 0; c--) { unsigned t = chunkSum[c]; chunkSum[c] = run; run += t; }
    }
    __syncthreads();
    if (tid < 64) {
        unsigned above = chunkSum[tid];
        #pragma unroll
        for (int b = 31; b >= 0; b--) {
            unsigned h = hist[tid * 32 + b];
            if (above < need && above + h >= need) { *outB = (unsigned)(tid * 32 + b); *outAbove = above; }
            above += h;
        }
    }
    __syncthreads();
}

__device__ __forceinline__ bool iou_gt(float kx1, float ky1, float kx2, float ky2, float ka,
                                       float x1, float y1, float x2, float y2, float ca) {
    float xx1 = fmaxf(kx1, x1), yy1 = fmaxf(ky1, y1);
    float xx2 = fminf(kx2, x2), yy2 = fminf(ky2, y2);
    float inter = fmaxf(xx2 - xx1, 0.f) * fmaxf(yy2 - yy1, 0.f);
    float iou = inter / (ka + ca - inter);          // 0/0 -> NaN -> not suppressed (matches JAX)
    return iou > 0.6f;
}

// ---------------- K2 (fused): hist2(full image) + collect + sort + NMS -----
#define FUSE_T 512
#define FUSE_SLICES 4
#define FUSE_ROUNDS 3      // slice rounds: ceil(NV4 / (FUSE_T*FUSE_SLICES))
#define FULL_ROUNDS 11     // full-image rounds: ceil(NV4 / FUSE_T)
#define CHUNK 64

__global__ void __launch_bounds__(FUSE_T) fused_kernel(float* __restrict__ out) {
    __shared__ unsigned h[2048];
    __shared__ unsigned chunkSum[64];
    __shared__ unsigned sB1, sAb1, sB2, sAb2;
    __shared__ int sLast;
    __shared__ unsigned long long keys[NCAP];
    __shared__ unsigned long long sorted[NCAP];
    // preloaded candidate state (final phase)
    __shared__ float Bx1[NCAP], By1[NCAP], Bx2[NCAP], By2[NCAP], Sar[NCAP], Ssc[NCAP];
    __shared__ int   Scl[NCAP];
    // NMS shared state
    __shared__ float kx1[100], ky1[100], kx2[100], ky2[100], ka[100];
    __shared__ int   supk[CHUNK];
    __shared__ unsigned long long mask[CHUNK];
    __shared__ int   kl[CHUNK];
    __shared__ unsigned sFlag[2];
    __shared__ int   sNew, sNK, sDone, sFast;

    int img = blockIdx.y;
    int tid = threadIdx.x;

    // slice-0 block prefills the output rows (off the final critical path;
    // ordered before final writes by the last-arrival barrier + fences)
    if (blockIdx.x == 0) {
        if (tid < 100) {
            out[img * 100 + tid]        = -1.f;
            out[1600 + img * 100 + tid] = -1.f;
        }
        for (int q = tid; q < 400; q += FUSE_T)
            out[3200 + img * 400 + q] = -1.f;
    }

    // ---- phase A: stage histA -> shared, find b1 --------------------------
    for (int i = tid; i < 2048; i += FUSE_T) h[i] = g_histA[img][i];
    __syncthreads();
    find_bin_sh(h, 256u, chunkSum, &sB1, &sAb1, tid);
    unsigned b1 = sB1;
    for (int i = tid; i < 2048; i += FUSE_T) h[i] = 0;    // reuse as hist2 accumulator
    __syncthreads();

    // ---- phase B: build the COMPLETE hist2 for this image in shared -------
    // (every slice block scans all scores; L2-resident broadcast reads, no
    //  cross-block merge, no spin barrier)
    const float4* sc4 = reinterpret_cast<const float4*>(g_scores + img * NA);
    #pragma unroll
    for (int it = 0; it < FULL_ROUNDS; it++) {
        int j = tid + it * FUSE_T;
        bool valid = j < NV4;
        float4 q = valid ? sc4[j] : make_float4(0.f, 0.f, 0.f, 0.f);
        unsigned u;
        // rare predicate -> plain shared atomics (no warp sync chains)
        u = __float_as_uint(q.x); if (valid && (u >> 21) == b1) atomicAdd(&h[(u >> 10) & 0x7FF], 1u);
        u = __float_as_uint(q.y); if (valid && (u >> 21) == b1) atomicAdd(&h[(u >> 10) & 0x7FF], 1u);
        u = __float_as_uint(q.z); if (valid && (u >> 21) == b1) atomicAdd(&h[(u >> 10) & 0x7FF], 1u);
        u = __float_as_uint(q.w); if (valid && (u >> 21) == b1) atomicAdd(&h[(u >> 10) & 0x7FF], 1u);
    }
    __syncthreads();
    find_bin_sh(h, 256u - sAb1, chunkSum, &sB2, &sAb2, tid);
    unsigned B = (b1 << 11) | sB2;     // 22-bit threshold key (identical in all blocks)

    // ---- phase C: collect this block's slice ------------------------------
    #pragma unroll
    for (int it = 0; it < FUSE_ROUNDS; it++) {
        int j = blockIdx.x * FUSE_T + tid + it * (FUSE_T * FUSE_SLICES);
        bool valid = j < NV4;
        float4 q = valid ? sc4[j] : make_float4(0.f, 0.f, 0.f, 0.f);
        float v[4] = {q.x, q.y, q.z, q.w};
        #pragma unroll
        for (int c = 0; c < 4; c++) {
            unsigned u = __float_as_uint(v[c]);
            unsigned k22 = u >> 10;
            if (valid && k22 >= B) {
                // key = (score_bits << 32) | (0x7FFFFFFF - anchor): ties ->
                // ascending anchor, matching the reference's stable order.
                unsigned long long key = ((unsigned long long)u << 32) |
                                         (unsigned)(0x7FFFFFFF - (4 * j + c));
                if (k22 > B) {
                    unsigned s = atomicAdd(&g_cnt[img][0], 1u);   // global >B count < 256
                    g_keys[img][s] = key;
                } else {
                    unsigned s = atomicAdd(&g_cnt[img][1], 1u);   // tie bucket
                    if (256u + s < NCAP) g_keys[img][256u + s] = key;
                }
            }
        }
    }

    // ---- last-arrival barrier: final phase runs in the last block ---------
    __threadfence();
    __syncthreads();
    if (tid == 0) {
        unsigned old = atomicAdd(&g_bar[img], 1u);
        sLast = (old == (unsigned)(FUSE_SLICES - 1));
    }
    __syncthreads();
    if (!sLast) return;
    __threadfence();

    // =================== FINAL PHASE (one block per image) ===================

    // load keys (count-masked; stale/unwritten slots -> PADKEY)
    unsigned gt = g_cnt[img][0];
    unsigned eq = g_cnt[img][1];
    {
        bool real = (tid < 256) ? ((unsigned)tid < gt) : ((unsigned)(tid - 256) < eq);
        keys[tid]   = real ? g_keys[img][tid] : PADKEY;
        sorted[tid] = PADKEY;
    }

    // self-clean scratch for the next launch
    for (int i = tid; i < 2048; i += FUSE_T) g_histA[img][i] = 0;
    if (tid < 2) g_cnt[img][tid] = 0;
    if (tid == 2) g_bar[img] = 0;
    __syncthreads();

    // rank sort: 1 key per thread; rank = #(strictly greater); broadcast LDS
    {
        unsigned long long my = keys[tid];
        const ulonglong2* K2 = reinterpret_cast<const ulonglong2*>(keys);
        int rank = 0;
        #pragma unroll 8
        for (int j2 = 0; j2 < NCAP / 2; j2++) {
            ulonglong2 p = K2[j2];
            rank += (p.x > my) + (p.y > my);
        }
        sorted[rank] = my;    // unique real keys -> dense exact ranks; pads collide benignly
    }
    __syncthreads();

    // pre-gather ALL candidate boxes/classes in one full-MLP pass
    {
        unsigned long long it = sorted[tid];
        float s = __uint_as_float((unsigned)(it >> 32));
        int anc = 0x7FFFFFFF - (int)(unsigned)(it & 0xffffffffULL);
        float4 bx = g_boxes[img * NA + anc];
        Bx1[tid] = bx.x; By1[tid] = bx.y; Bx2[tid] = bx.z; By2[tid] = bx.w;
        Sar[tid] = (bx.z - bx.x) * (bx.w - bx.y);
        Scl[tid] = g_classes[img * NA + anc];
        Ssc[tid] = s;
    }
    __syncthreads();

    // NMS over sorted candidates (all state in shared)
    if (tid == 0) { sNK = 0; sDone = 0; }
    __syncthreads();

    for (int base = 0; base < NCAP; base += CHUNK) {
        if (sDone) break;

        if (tid < CHUNK) { supk[tid] = 0; mask[tid] = 0ULL; }
        __syncthreads();

        int nk = sNK;
        {
            int c = tid & (CHUNK - 1);
            int part = tid >> 6;            // 0..7
            float x1 = Bx1[base + c], y1 = By1[base + c];
            float x2 = Bx2[base + c], y2 = By2[base + c], ar = Sar[base + c];
            bool any = false;
            for (int j = part; j < nk; j += 8)
                any |= iou_gt(kx1[j], ky1[j], kx2[j], ky2[j], ka[j], x1, y1, x2, y2, ar);
            if (any) supk[c] = 1;           // benign race: all writers store 1
        }

        for (int p = tid; p < CHUNK * CHUNK; p += FUSE_T) {
            int c = p >> 6, j = p & (CHUNK - 1);
            if (c < j) {
                if (iou_gt(Bx1[base + c], By1[base + c], Bx2[base + c], By2[base + c], Sar[base + c],
                           Bx1[base + j], By1[base + j], Bx2[base + j], By2[base + j], Sar[base + j]))
                    atomicOr(&mask[c], 1ULL << j);
            }
        }
        __syncthreads();

        // fast path: no suppression anywhere in chunk and all scores valid
        if (tid < CHUNK) {
            bool bad = supk[tid] || (mask[tid] != 0ULL) || (Ssc[base + tid] <= 0.01f);
            unsigned bb = __ballot_sync(FULLMASK, bad);
            if ((tid & 31) == 0) sFlag[tid >> 5] = bb;
        }
        __syncthreads();

        if (tid == 0) {
            if ((sFlag[0] | sFlag[1]) == 0u) {
                int nnew = min(CHUNK, 100 - sNK);
                sNew = nnew; sFast = 1;
                if (sNK + nnew >= 100) sDone = 1;
            } else {
                sFast = 0;
                unsigned long long sup = 0;
                int nnew = 0;
                int done = 0;
                for (int c = 0; c < CHUNK; c++) {
                    if (Ssc[base + c] <= 0.01f) { done = 1; break; }  // sorted -> rest invalid
                    if (supk[c] || ((sup >> c) & 1ULL)) continue;
                    kl[nnew++] = c;
                    sup |= mask[c];
                    if (sNK + nnew == 100) { done = 1; break; }
                }
                sNew = nnew;
                if (done) sDone = 1;
            }
        }
        __syncthreads();

        if (tid < sNew) {
            int c = base + (sFast ? tid : kl[tid]);
            int pos = sNK + tid;
            kx1[pos] = Bx1[c]; ky1[pos] = By1[c];
            kx2[pos] = Bx2[c]; ky2[pos] = By2[c];
            ka[pos]  = Sar[c];
            out[img * 100 + pos]        = Ssc[c];
            out[1600 + img * 100 + pos] = (float)Scl[c];
            int ob = 3200 + img * 400 + pos * 4;
            out[ob]     = Bx1[c];
            out[ob + 1] = By1[c];
            out[ob + 2] = Bx2[c];
            out[ob + 3] = By2[c];
        }
        __syncthreads();
        if (tid == 0) sNK += sNew;
        __syncthreads();
    }
}

// ---------------- launch ---------------------------------------------------
extern "C" void kernel_launch(void* const* d_in, const int* in_sizes, int n_in,
                              void* d_out, int out_size) {
    DecodeParams P;
    for (int l = 0; l < 5; l++) {
        P.cls[l] = (const float*)d_in[4 * l + 0];
        P.reg[l] = (const float*)d_in[4 * l + 1];
        P.ctr[l] = (const float*)d_in[4 * l + 2];
        P.pos[l] = (const float*)d_in[4 * l + 3];
    }
    dim3 dgrid(341, BATCH);
    decode_kernel<<<dgrid, DEC_T>>>(P);
    dim3 fgrid(FUSE_SLICES, BATCH);
    fused_kernel<<<fgrid, FUSE_T>>>((float*)d_out);
}